// round 14
// baseline (speedup 1.0000x reference)
#include <cuda_runtime.h>
#include <cuda_fp16.h>
#include <cstdint>

#define NN      100000
#define NE      1600000
#define HID     256
#define KDIM    256
#define NSLOTS  800
#define SCAN_BLK 1024
#define NSCAN   ((NN + SCAN_BLK - 1) / SCAN_BLK)   // 98

// ---------------- scratch ----------------
__device__ __align__(128) __half g_z16[(size_t)NN * HID];   // GEMM out (fp16)
__device__ __align__(128) __half g_h16[(size_t)NN * HID];   // tanh(agg1) (fp16)
__device__ __align__(128) __half g_w16[2 * KDIM * HID];     // fp16 W1, W2
__device__ __align__(128) float  g_sums[NSLOTS * HID];
__device__ float g_cnt [NSLOTS];
__device__ int   g_deg [NN];
__device__ int   g_off [NN];
__device__ int   g_cursor[NN];
__device__ int   g_part[NSCAN];
__device__ int   g_csr [NE];

// ---------------- helpers ----------------
__device__ __forceinline__ void red_add_v4(float4* p, const float4 v) {
    asm volatile("red.global.add.v4.f32 [%0], {%1, %2, %3, %4};"
                 :: "l"(p), "f"(v.x), "f"(v.y), "f"(v.z), "f"(v.w)
                 : "memory");
}
__device__ __forceinline__ uint32_t pack_h2(float a, float b) {
    __half2 h = __floats2half2_rn(a, b);
    return *reinterpret_cast<uint32_t*>(&h);
}

// ---------------- zero / CSR build ----------------
__global__ void zero_misc_kernel() {
    int i = blockIdx.x * blockDim.x + threadIdx.x;
    if (i < NN)            g_deg[i]  = 0;
    if (i < NSLOTS * HID)  g_sums[i] = 0.f;
    if (i < NSLOTS)        g_cnt[i]  = 0.f;
}
__global__ void hist_kernel(const int* __restrict__ edst) {
    int e = blockIdx.x * blockDim.x + threadIdx.x;
    if (e < NE) atomicAdd(&g_deg[edst[e]], 1);
}
__global__ void scan1_kernel() {
    __shared__ int sh[256];
    int tid = threadIdx.x;
    int base = blockIdx.x * SCAN_BLK + tid * 4;
    int s = 0;
    if (base < NN) {
        int4 v = *reinterpret_cast<const int4*>(g_deg + base);
        s = v.x + v.y + v.z + v.w;
    }
    sh[tid] = s; __syncthreads();
    for (int o = 128; o > 0; o >>= 1) {
        if (tid < o) sh[tid] += sh[tid + o];
        __syncthreads();
    }
    if (tid == 0) g_part[blockIdx.x] = sh[0];
}
__global__ void scan2_kernel() {
    int lane = threadIdx.x;
    int base = lane * 4;
    int v[4], tot = 0;
#pragma unroll
    for (int j = 0; j < 4; j++) {
        v[j] = (base + j < NSCAN) ? g_part[base + j] : 0;
        tot += v[j];
    }
    int inc = tot;
#pragma unroll
    for (int o = 1; o < 32; o <<= 1) {
        int n = __shfl_up_sync(0xFFFFFFFFu, inc, o);
        if (lane >= o) inc += n;
    }
    int run = inc - tot;
#pragma unroll
    for (int j = 0; j < 4; j++) {
        if (base + j < NSCAN) g_part[base + j] = run;
        run += v[j];
    }
}
__global__ void scan3_kernel() {
    __shared__ int sh[256];
    int tid = threadIdx.x;
    int base = blockIdx.x * SCAN_BLK + tid * 4;
    int4 v = make_int4(0, 0, 0, 0);
    if (base < NN) v = *reinterpret_cast<const int4*>(g_deg + base);
    int t = v.x + v.y + v.z + v.w;
    sh[tid] = t; __syncthreads();
    for (int o = 1; o < 256; o <<= 1) {
        int add = (tid >= o) ? sh[tid - o] : 0;
        __syncthreads();
        sh[tid] += add;
        __syncthreads();
    }
    int excl = sh[tid] - t + g_part[blockIdx.x];
    if (base < NN) {
        int4 o;
        o.x = excl; o.y = o.x + v.x; o.z = o.y + v.y; o.w = o.z + v.z;
        *reinterpret_cast<int4*>(g_off + base)    = o;
        *reinterpret_cast<int4*>(g_cursor + base) = o;
    }
}
__global__ void fill_csr_kernel(const int* __restrict__ esrc, const int* __restrict__ edst) {
    int e = blockIdx.x * blockDim.x + threadIdx.x;
    if (e >= NE) return;
    int d   = edst[e];
    int pos = atomicAdd(&g_cursor[d], 1);
    g_csr[pos] = esrc[e];
}

// ---------------- fp16 weight pre-conversion ----------------
__global__ void conv_w_kernel(const float* __restrict__ W1, const float* __restrict__ W2) {
    int i = blockIdx.x * 256 + threadIdx.x;              // 0..32767 float4s
    const float4* src = (i < 16384) ? reinterpret_cast<const float4*>(W1)
                                    : reinterpret_cast<const float4*>(W2) - 16384;
    float4 v = src[i];
    uint2 o;
    o.x = pack_h2(v.x, v.y);
    o.y = pack_h2(v.z, v.w);
    reinterpret_cast<uint2*>(g_w16)[i] = o;
}

// ---------------- fp16 mma.sync GEMM, cp.async 4-stage, templated A dtype ----
// CTA 128x128, BK=32, warp tile 64x32 (8 warps, 2x4).
// A32=1: A = Aptr (fp32, stride-36 stage, packed to fp16 at frag load).
// A32=0: A = g_h16 (fp16, stride-40 stage) -- resolved in DEVICE code.
#define BK      32
#define NCH     (KDIM / BK)            // 8
#define AS32    36                     // floats per A row (fp32 stage)
#define AS16    40                     // halves per A row (fp16 stage)
#define BS_H    136                    // halves per B k-row
#define B_STG_B (BK * BS_H * 2)        // 8704 B
#define NSTAGE  4

__device__ __forceinline__ void mma_f16(float* d, const uint32_t* a, const uint32_t* b) {
    asm volatile(
        "mma.sync.aligned.m16n8k16.row.col.f32.f16.f16.f32 "
        "{%0,%1,%2,%3}, {%4,%5,%6,%7}, {%8,%9}, {%0,%1,%2,%3};"
        : "+f"(d[0]), "+f"(d[1]), "+f"(d[2]), "+f"(d[3])
        : "r"(a[0]), "r"(a[1]), "r"(a[2]), "r"(a[3]), "r"(b[0]), "r"(b[1]));
}
__device__ __forceinline__ void ldsm_x4_trans(uint32_t* r, uint32_t addr) {
    asm volatile("ldmatrix.sync.aligned.m8n8.x4.trans.shared.b16 {%0,%1,%2,%3}, [%4];"
                 : "=r"(r[0]), "=r"(r[1]), "=r"(r[2]), "=r"(r[3]) : "r"(addr));
}
__device__ __forceinline__ void cp16(uint32_t dst, const void* src, int sz) {
    asm volatile("cp.async.cg.shared.global [%0], [%1], 16, %2;"
                 :: "r"(dst), "l"(src), "r"(sz));
}

template <int A32>
__device__ __forceinline__ void gemm_fill_async(const float* __restrict__ Aptr,
                                                const __half* __restrict__ Wp,
                                                int m_base, int n_base, int M, int k0,
                                                uint32_t Au, uint32_t Bu, int tid) {
    if (A32) {
        const float* A = Aptr;
#pragma unroll
        for (int l = 0; l < 4; l++) {
            int ch  = tid + l * 256;         // 0..1023
            int r   = ch >> 3;
            int c4  = (ch & 7) << 2;
            int gm  = m_base + r;
            cp16(Au + (r * AS32 + c4) * 4,
                 A + (size_t)((gm < M) ? gm : 0) * KDIM + k0 + c4,
                 (gm < M) ? 16 : 0);
        }
    } else {
        const __half* A = g_h16;             // device-side symbol resolution
#pragma unroll
        for (int l = 0; l < 2; l++) {
            int ch  = tid + l * 256;         // 0..511
            int r   = ch >> 2;
            int c8  = (ch & 3) << 3;
            int gm  = m_base + r;
            cp16(Au + (r * AS16 + c8) * 2,
                 A + (size_t)((gm < M) ? gm : 0) * KDIM + k0 + c8,
                 (gm < M) ? 16 : 0);
        }
    }
    // B tile: 32 k-rows x 128 halves; 16 chunks/row; 2/thread
#pragma unroll
    for (int l = 0; l < 2; l++) {
        int ch  = tid + l * 256;             // 0..511
        int k   = ch >> 4;
        int n8  = (ch & 15) << 3;
        cp16(Bu + (k * BS_H + n8) * 2,
             Wp + (size_t)(k0 + k) * HID + n_base + n8, 16);
    }
    asm volatile("cp.async.commit_group;" ::: "memory");
}

template <int A32>
__global__ __launch_bounds__(256, 2)
void gemm_mma_kernel(const float* __restrict__ Aptr, const float* __restrict__ bias,
                     int M, int w_sel) {
    extern __shared__ char smem_raw[];
    const __half* __restrict__ Wp = g_w16 + (size_t)w_sel * KDIM * HID;

    const int tid    = threadIdx.x;
    const int wid    = tid >> 5;
    const int lane   = tid & 31;
    const int warp_m = wid >> 2;
    const int warp_n = wid & 3;
    const int m_base = blockIdx.y * 128;
    const int n_base = blockIdx.x * 128;

    constexpr int A_STG_B = A32 ? (128 * AS32 * 4) : (128 * AS16 * 2);
    uint32_t smem_u = (uint32_t)__cvta_generic_to_shared(smem_raw);
    uint32_t Au[NSTAGE], Bu[NSTAGE];
#pragma unroll
    for (int s = 0; s < NSTAGE; s++) {
        Au[s] = smem_u + s * A_STG_B;
        Bu[s] = smem_u + NSTAGE * A_STG_B + s * B_STG_B;
    }

    float acc[4][4][4];
#pragma unroll
    for (int i = 0; i < 4; i++)
#pragma unroll
        for (int j = 0; j < 4; j++)
#pragma unroll
            for (int f = 0; f < 4; f++) acc[i][j][f] = 0.f;

    gemm_fill_async<A32>(Aptr, Wp, m_base, n_base, M, 0 * BK, Au[0], Bu[0], tid);
    gemm_fill_async<A32>(Aptr, Wp, m_base, n_base, M, 1 * BK, Au[1], Bu[1], tid);
    gemm_fill_async<A32>(Aptr, Wp, m_base, n_base, M, 2 * BK, Au[2], Bu[2], tid);

    const int g      = lane >> 2;
    const int cth    = lane & 3;
    const int ld_row = lane & 15;
    const int ld_grp = (lane >> 4) << 3;

    for (int c = 0; c < NCH; c++) {
        int s = c % NSTAGE;
        // Tail-correct wait: groups 0..c must be complete.
        {
            int rem = NCH - 1 - c;
            if (rem >= 2)
                asm volatile("cp.async.wait_group 2;" ::: "memory");
            else if (rem == 1)
                asm volatile("cp.async.wait_group 1;" ::: "memory");
            else
                asm volatile("cp.async.wait_group 0;" ::: "memory");
        }
        __syncthreads();

        if (c + 3 < NCH)
            gemm_fill_async<A32>(Aptr, Wp, m_base, n_base, M, (c + 3) * BK,
                                 Au[(c + 3) % NSTAGE], Bu[(c + 3) % NSTAGE], tid);

#pragma unroll
        for (int ks = 0; ks < 2; ks++) {
            uint32_t bfr[4][2];
#pragma unroll
            for (int hn = 0; hn < 2; hn++) {
                uint32_t hidx = (uint32_t)((ks * 16 + ld_row) * BS_H
                                           + warp_n * 32 + hn * 16 + ld_grp);
                uint32_t r[4];
                ldsm_x4_trans(r, Bu[s] + hidx * 2);
                bfr[2 * hn][0]     = r[0];
                bfr[2 * hn][1]     = r[1];
                bfr[2 * hn + 1][0] = r[2];
                bfr[2 * hn + 1][1] = r[3];
            }
#pragma unroll
            for (int mt = 0; mt < 4; mt++) {
                uint32_t afr[4];
                if (A32) {
                    const float* Ac = reinterpret_cast<const float*>(smem_raw + s * A_STG_B);
                    int base = (warp_m * 64 + mt * 16 + g) * AS32 + ks * 16 + 2 * cth;
                    float2 v0 = *reinterpret_cast<const float2*>(Ac + base);
                    float2 v1 = *reinterpret_cast<const float2*>(Ac + base + 8 * AS32);
                    float2 v2 = *reinterpret_cast<const float2*>(Ac + base + 8);
                    float2 v3 = *reinterpret_cast<const float2*>(Ac + base + 8 * AS32 + 8);
                    afr[0] = pack_h2(v0.x, v0.y);
                    afr[1] = pack_h2(v1.x, v1.y);
                    afr[2] = pack_h2(v2.x, v2.y);
                    afr[3] = pack_h2(v3.x, v3.y);
                } else {
                    const __half* Ac = reinterpret_cast<const __half*>(smem_raw + s * A_STG_B);
                    int base = (warp_m * 64 + mt * 16 + g) * AS16 + ks * 16 + 2 * cth;
                    afr[0] = *reinterpret_cast<const uint32_t*>(Ac + base);
                    afr[1] = *reinterpret_cast<const uint32_t*>(Ac + base + 8 * AS16);
                    afr[2] = *reinterpret_cast<const uint32_t*>(Ac + base + 8);
                    afr[3] = *reinterpret_cast<const uint32_t*>(Ac + base + 8 * AS16 + 8);
                }
#pragma unroll
                for (int nt = 0; nt < 4; nt++)
                    mma_f16(acc[mt][nt], afr, bfr[nt]);
            }
        }
        __syncthreads();
    }

    // epilogue: fp32 acc + bias -> fp16 store
#pragma unroll
    for (int mt = 0; mt < 4; mt++) {
        int r0 = m_base + warp_m * 64 + mt * 16 + g;
        int r1 = r0 + 8;
#pragma unroll
        for (int nt = 0; nt < 4; nt++) {
            int col = n_base + warp_n * 32 + nt * 8 + cth * 2;
            float b0 = __ldg(bias + col);
            float b1 = __ldg(bias + col + 1);
            if (r0 < M) {
                uint32_t o = pack_h2(acc[mt][nt][0] + b0, acc[mt][nt][1] + b1);
                *reinterpret_cast<uint32_t*>(g_z16 + (size_t)r0 * HID + col) = o;
            }
            if (r1 < M) {
                uint32_t o = pack_h2(acc[mt][nt][2] + b0, acc[mt][nt][3] + b1);
                *reinterpret_cast<uint32_t*>(g_z16 + (size_t)r1 * HID + col) = o;
            }
        }
    }
}

#define GEMM1_SMEM (NSTAGE * (128 * AS32 * 4 + B_STG_B))   // 108544
#define GEMM2_SMEM (NSTAGE * (128 * AS16 * 2 + B_STG_B))   // 75776

// ---------------- fp16 gather-aggregate (CSR), warp per node, unroll 8 -------
__device__ __forceinline__ void acc_row(float* a, const uint4& v) {
    const uint32_t* w = &v.x;
#pragma unroll
    for (int j = 0; j < 4; j++) {
        float2 f = __half22float2(*reinterpret_cast<const __half2*>(w + j));
        a[2 * j]     += f.x;
        a[2 * j + 1] += f.y;
    }
}

__device__ __forceinline__ void gather_node16(int node, int lane, float* a /*[8]*/) {
    int start = g_off[node];
    int d     = g_deg[node];
    const uint4* Z = reinterpret_cast<const uint4*>(g_z16);   // 32 uint4 per row
#pragma unroll
    for (int j = 0; j < 8; j++) a[j] = 0.f;
    int i = 0;
    for (; i + 8 <= d; i += 8) {
        int s[8];
#pragma unroll
        for (int j = 0; j < 8; j++) s[j] = __ldg(&g_csr[start + i + j]);
        uint4 v[8];
#pragma unroll
        for (int j = 0; j < 8; j++) v[j] = __ldg(Z + (size_t)s[j] * 32 + lane);
#pragma unroll
        for (int j = 0; j < 8; j++) acc_row(a, v[j]);
    }
    for (; i < d; i++) {
        int s0 = __ldg(&g_csr[start + i]);
        uint4 v0 = __ldg(Z + (size_t)s0 * 32 + lane);
        acc_row(a, v0);
    }
}

__global__ void agg1_kernel() {
    int node = (blockIdx.x * blockDim.x + threadIdx.x) >> 5;
    int lane = threadIdx.x & 31;
    if (node >= NN) return;
    float a[8];
    gather_node16(node, lane, a);
    uint4 o;
    uint32_t* w = &o.x;
#pragma unroll
    for (int j = 0; j < 4; j++)
        w[j] = pack_h2(tanhf(a[2 * j]), tanhf(a[2 * j + 1]));
    reinterpret_cast<uint4*>(g_h16)[(size_t)node * 32 + lane] = o;   // L2-resident for GEMM2
}

__global__ void agg2_pool_kernel(const int* __restrict__ seg) {
    int node = (blockIdx.x * blockDim.x + threadIdx.x) >> 5;
    int lane = threadIdx.x & 31;
    if (node >= NN) return;
    float a[8];
    gather_node16(node, lane, a);
    int s = __ldg(seg + node);
    float4* dp = reinterpret_cast<float4*>(g_sums + (size_t)s * HID + lane * 8);
    float4 t0 = make_float4(tanhf(a[0]), tanhf(a[1]), tanhf(a[2]), tanhf(a[3]));
    float4 t1 = make_float4(tanhf(a[4]), tanhf(a[5]), tanhf(a[6]), tanhf(a[7]));
    red_add_v4(dp,     t0);
    red_add_v4(dp + 1, t1);
    if (lane == 0) atomicAdd(&g_cnt[s], 1.0f);
}

__global__ void finalize_kernel(float* __restrict__ out) {
    int i = blockIdx.x * blockDim.x + threadIdx.x;
    if (i < NSLOTS * HID) {
        float c = g_cnt[i >> 8];
        out[i] = g_sums[i] / fmaxf(c, 1.0f);
    }
}

// ---------------- launch ----------------
extern "C" void kernel_launch(void* const* d_in, const int* in_sizes, int n_in,
                              void* d_out, int out_size) {
    const float* h    = (const float*)d_in[0];
    const float* W1   = (const float*)d_in[1];
    const float* b1   = (const float*)d_in[2];
    const float* W2   = (const float*)d_in[3];
    const float* b2   = (const float*)d_in[4];
    const int*   esrc = (const int*)d_in[5];
    const int*   edst = (const int*)d_in[6];
    const int*   seg  = (const int*)d_in[7];
    float*       out  = (float*)d_out;

    const int M = in_sizes[0] / HID;   // 100000

    static cudaStream_t s2 = nullptr;
    static cudaEvent_t  evA = nullptr, evB = nullptr;
    static int inited = 0;
    if (!inited) {
        cudaStreamCreateWithFlags(&s2, cudaStreamNonBlocking);
        cudaEventCreateWithFlags(&evA, cudaEventDisableTiming);
        cudaEventCreateWithFlags(&evB, cudaEventDisableTiming);
        cudaFuncSetAttribute(gemm_mma_kernel<1>,
                             cudaFuncAttributeMaxDynamicSharedMemorySize, GEMM1_SMEM);
        cudaFuncSetAttribute(gemm_mma_kernel<0>,
                             cudaFuncAttributeMaxDynamicSharedMemorySize, GEMM2_SMEM);
        inited = 1;
    }

    dim3 gemm_grid(HID / 128, (M + 127) / 128);        // (2, 782)
    int  agg_blocks  = (M * 32 + 255) / 256;
    int  edge_blocks = (NE + 255) / 256;

    // ---- fork: CSR build on side stream ----
    cudaEventRecord(evA, 0);
    cudaStreamWaitEvent(s2, evA, 0);
    zero_misc_kernel<<<(NSLOTS * HID + 255) / 256, 256, 0, s2>>>();
    hist_kernel<<<edge_blocks, 256, 0, s2>>>(edst);
    scan1_kernel<<<NSCAN, 256, 0, s2>>>();
    scan2_kernel<<<1, 32, 0, s2>>>();
    scan3_kernel<<<NSCAN, 256, 0, s2>>>();
    fill_csr_kernel<<<edge_blocks, 256, 0, s2>>>(esrc, edst);
    cudaEventRecord(evB, s2);

    // ---- main stream: conv_w + GEMM1 (fp32 A directly; overlaps CSR build) ----
    conv_w_kernel<<<128, 256>>>(W1, W2);
    gemm_mma_kernel<1><<<gemm_grid, 256, GEMM1_SMEM>>>(h, b1, M, 0);

    // ---- join: CSR needed from here on ----
    cudaStreamWaitEvent(0, evB, 0);
    agg1_kernel<<<agg_blocks, 256>>>();

    gemm_mma_kernel<0><<<gemm_grid, 256, GEMM2_SMEM>>>(nullptr, b2, M, 1);
    agg2_pool_kernel<<<agg_blocks, 256>>>(seg);

    finalize_kernel<<<(NSLOTS * HID + 255) / 256, 256>>>(out);
}

// round 15
// speedup vs baseline: 1.0474x; 1.0474x over previous
#include <cuda_runtime.h>
#include <cuda_fp16.h>
#include <cstdint>

#define NN      100000
#define NE      1600000
#define HID     256
#define KDIM    256
#define NSLOTS  800
#define SCAN_BLK 1024
#define NSCAN   ((NN + SCAN_BLK - 1) / SCAN_BLK)   // 98

// ---------------- scratch ----------------
__device__ __align__(128) __half g_z16[(size_t)NN * HID];   // GEMM out (fp16)
__device__ __align__(128) __half g_h16[(size_t)NN * HID];   // tanh(agg1) (fp16)
__device__ __align__(128) __half g_x16[(size_t)NN * HID];   // fp16 input x
__device__ __align__(128) __half g_w16[2 * KDIM * HID];     // fp16 W1, W2
__device__ __align__(128) float  g_sums[NSLOTS * HID];
__device__ float g_cnt [NSLOTS];
__device__ int   g_deg [NN];
__device__ int   g_off [NN];
__device__ int   g_cursor[NN];
__device__ int   g_part[NSCAN];
__device__ int   g_csr [NE];

// ---------------- helpers ----------------
__device__ __forceinline__ void red_add_v4(float4* p, const float4 v) {
    asm volatile("red.global.add.v4.f32 [%0], {%1, %2, %3, %4};"
                 :: "l"(p), "f"(v.x), "f"(v.y), "f"(v.z), "f"(v.w)
                 : "memory");
}
__device__ __forceinline__ uint32_t pack_h2(float a, float b) {
    __half2 h = __floats2half2_rn(a, b);
    return *reinterpret_cast<uint32_t*>(&h);
}

// ---------------- zero / CSR build ----------------
__global__ void zero_misc_kernel() {
    int i = blockIdx.x * blockDim.x + threadIdx.x;
    if (i < NN)            g_deg[i]  = 0;
    if (i < NSLOTS * HID)  g_sums[i] = 0.f;
    if (i < NSLOTS)        g_cnt[i]  = 0.f;
}
__global__ void hist_kernel(const int* __restrict__ edst) {
    int e = blockIdx.x * blockDim.x + threadIdx.x;
    if (e < NE) atomicAdd(&g_deg[edst[e]], 1);
}
__global__ void scan1_kernel() {
    __shared__ int sh[256];
    int tid = threadIdx.x;
    int base = blockIdx.x * SCAN_BLK + tid * 4;
    int s = 0;
    if (base < NN) {
        int4 v = *reinterpret_cast<const int4*>(g_deg + base);
        s = v.x + v.y + v.z + v.w;
    }
    sh[tid] = s; __syncthreads();
    for (int o = 128; o > 0; o >>= 1) {
        if (tid < o) sh[tid] += sh[tid + o];
        __syncthreads();
    }
    if (tid == 0) g_part[blockIdx.x] = sh[0];
}
__global__ void scan2_kernel() {
    int lane = threadIdx.x;
    int base = lane * 4;
    int v[4], tot = 0;
#pragma unroll
    for (int j = 0; j < 4; j++) {
        v[j] = (base + j < NSCAN) ? g_part[base + j] : 0;
        tot += v[j];
    }
    int inc = tot;
#pragma unroll
    for (int o = 1; o < 32; o <<= 1) {
        int n = __shfl_up_sync(0xFFFFFFFFu, inc, o);
        if (lane >= o) inc += n;
    }
    int run = inc - tot;
#pragma unroll
    for (int j = 0; j < 4; j++) {
        if (base + j < NSCAN) g_part[base + j] = run;
        run += v[j];
    }
}
__global__ void scan3_kernel() {
    __shared__ int sh[256];
    int tid = threadIdx.x;
    int base = blockIdx.x * SCAN_BLK + tid * 4;
    int4 v = make_int4(0, 0, 0, 0);
    if (base < NN) v = *reinterpret_cast<const int4*>(g_deg + base);
    int t = v.x + v.y + v.z + v.w;
    sh[tid] = t; __syncthreads();
    for (int o = 1; o < 256; o <<= 1) {
        int add = (tid >= o) ? sh[tid - o] : 0;
        __syncthreads();
        sh[tid] += add;
        __syncthreads();
    }
    int excl = sh[tid] - t + g_part[blockIdx.x];
    if (base < NN) {
        int4 o;
        o.x = excl; o.y = o.x + v.x; o.z = o.y + v.y; o.w = o.z + v.z;
        *reinterpret_cast<int4*>(g_off + base)    = o;
        *reinterpret_cast<int4*>(g_cursor + base) = o;
    }
}
__global__ void fill_csr_kernel(const int* __restrict__ esrc, const int* __restrict__ edst) {
    int e = blockIdx.x * blockDim.x + threadIdx.x;
    if (e >= NE) return;
    int d   = edst[e];
    int pos = atomicAdd(&g_cursor[d], 1);
    g_csr[pos] = esrc[e];
}

// ---------------- fp16 pre-conversion ----------------
__global__ void conv_x_kernel(const float* __restrict__ x) {
    size_t i = (size_t)blockIdx.x * 256 + threadIdx.x;   // 6.4M float4s
    float4 v = reinterpret_cast<const float4*>(x)[i];
    uint2 o;
    o.x = pack_h2(v.x, v.y);
    o.y = pack_h2(v.z, v.w);
    reinterpret_cast<uint2*>(g_x16)[i] = o;
}
__global__ void conv_w_kernel(const float* __restrict__ W1, const float* __restrict__ W2) {
    int i = blockIdx.x * 256 + threadIdx.x;              // 0..32767 float4s
    const float4* src = (i < 16384) ? reinterpret_cast<const float4*>(W1)
                                    : reinterpret_cast<const float4*>(W2) - 16384;
    float4 v = src[i];
    uint2 o;
    o.x = pack_h2(v.x, v.y);
    o.y = pack_h2(v.z, v.w);
    reinterpret_cast<uint2*>(g_w16)[i] = o;
}

// ---------------- fp16 mma.sync GEMM, cp.async 4-stage ----------------
// CTA 128x128, BK=32, warp tile 64x32 (8 warps, 2x4). A selected in device code.
#define BK      32
#define NCH     (KDIM / BK)            // 8
#define AS_H    40                     // halves per A row
#define BS_H    136                    // halves per B k-row
#define A_STG_B (128 * AS_H * 2)       // 10240 B
#define B_STG_B (BK * BS_H * 2)        // 8704 B
#define NSTAGE  4
#define GEMM_SMEM_BYTES (NSTAGE * (A_STG_B + B_STG_B))   // 75776

__device__ __forceinline__ void mma_f16(float* d, const uint32_t* a, const uint32_t* b) {
    asm volatile(
        "mma.sync.aligned.m16n8k16.row.col.f32.f16.f16.f32 "
        "{%0,%1,%2,%3}, {%4,%5,%6,%7}, {%8,%9}, {%0,%1,%2,%3};"
        : "+f"(d[0]), "+f"(d[1]), "+f"(d[2]), "+f"(d[3])
        : "r"(a[0]), "r"(a[1]), "r"(a[2]), "r"(a[3]), "r"(b[0]), "r"(b[1]));
}
__device__ __forceinline__ void ldsm_x4_trans(uint32_t* r, uint32_t addr) {
    asm volatile("ldmatrix.sync.aligned.m8n8.x4.trans.shared.b16 {%0,%1,%2,%3}, [%4];"
                 : "=r"(r[0]), "=r"(r[1]), "=r"(r[2]), "=r"(r[3]) : "r"(addr));
}
__device__ __forceinline__ void cp16(uint32_t dst, const void* src, int sz) {
    asm volatile("cp.async.cg.shared.global [%0], [%1], 16, %2;"
                 :: "r"(dst), "l"(src), "r"(sz));
}

__device__ __forceinline__ void gemm_fill_async(const __half* __restrict__ A,
                                                const __half* __restrict__ Wp,
                                                int m_base, int n_base, int M, int k0,
                                                uint32_t Au, uint32_t Bu, int tid) {
    // A: 128 rows x 32 halves; 16B = 8 halves; 4 chunks/row; 2/thread
#pragma unroll
    for (int l = 0; l < 2; l++) {
        int ch  = tid + l * 256;            // 0..511
        int r   = ch >> 2;
        int c8  = (ch & 3) << 3;
        int gm  = m_base + r;
        cp16(Au + (r * AS_H + c8) * 2,
             A + (size_t)((gm < M) ? gm : 0) * KDIM + k0 + c8,
             (gm < M) ? 16 : 0);
    }
    // B: 32 k-rows x 128 halves; 16 chunks/row; 2/thread
#pragma unroll
    for (int l = 0; l < 2; l++) {
        int ch  = tid + l * 256;            // 0..511
        int k   = ch >> 4;
        int n8  = (ch & 15) << 3;
        cp16(Bu + (k * BS_H + n8) * 2,
             Wp + (size_t)(k0 + k) * HID + n_base + n8, 16);
    }
    asm volatile("cp.async.commit_group;" ::: "memory");
}

__global__ __launch_bounds__(256, 2)
void gemm_mma_kernel(const float* __restrict__ bias, int M, int a_sel, int w_sel) {
    extern __shared__ __half smem[];
    const __half* __restrict__ A  = a_sel ? g_h16 : g_x16;   // device-side resolve
    const __half* __restrict__ Wp = g_w16 + (size_t)w_sel * KDIM * HID;

    const int tid    = threadIdx.x;
    const int wid    = tid >> 5;
    const int lane   = tid & 31;
    const int warp_m = wid >> 2;
    const int warp_n = wid & 3;
    const int m_base = blockIdx.y * 128;
    const int n_base = blockIdx.x * 128;

    uint32_t smem_u = (uint32_t)__cvta_generic_to_shared(smem);
    const __half* As[NSTAGE];
    uint32_t Au[NSTAGE], Bu[NSTAGE];
#pragma unroll
    for (int s = 0; s < NSTAGE; s++) {
        As[s] = smem + s * (A_STG_B / 2);
        Au[s] = smem_u + s * A_STG_B;
        Bu[s] = smem_u + NSTAGE * A_STG_B + s * B_STG_B;
    }

    float acc[4][4][4];
#pragma unroll
    for (int i = 0; i < 4; i++)
#pragma unroll
        for (int j = 0; j < 4; j++)
#pragma unroll
            for (int f = 0; f < 4; f++) acc[i][j][f] = 0.f;

    gemm_fill_async(A, Wp, m_base, n_base, M, 0 * BK, Au[0], Bu[0], tid);
    gemm_fill_async(A, Wp, m_base, n_base, M, 1 * BK, Au[1], Bu[1], tid);
    gemm_fill_async(A, Wp, m_base, n_base, M, 2 * BK, Au[2], Bu[2], tid);

    const int g      = lane >> 2;
    const int cth    = lane & 3;
    const int ld_row = lane & 15;
    const int ld_grp = (lane >> 4) << 3;

    for (int c = 0; c < NCH; c++) {
        int s = c % NSTAGE;
        // Tail-correct wait: groups 0..c must be complete before consuming stage s.
        {
            int rem = NCH - 1 - c;
            if (rem >= 2)
                asm volatile("cp.async.wait_group 2;" ::: "memory");
            else if (rem == 1)
                asm volatile("cp.async.wait_group 1;" ::: "memory");
            else
                asm volatile("cp.async.wait_group 0;" ::: "memory");
        }
        __syncthreads();

        if (c + 3 < NCH)
            gemm_fill_async(A, Wp, m_base, n_base, M, (c + 3) * BK,
                            Au[(c + 3) % NSTAGE], Bu[(c + 3) % NSTAGE], tid);

        const __half* Ac = As[s];
#pragma unroll
        for (int ks = 0; ks < 2; ks++) {
            uint32_t bfr[4][2];
#pragma unroll
            for (int hn = 0; hn < 2; hn++) {
                uint32_t hidx = (uint32_t)((ks * 16 + ld_row) * BS_H
                                           + warp_n * 32 + hn * 16 + ld_grp);
                uint32_t r[4];
                ldsm_x4_trans(r, Bu[s] + hidx * 2);
                bfr[2 * hn][0]     = r[0];
                bfr[2 * hn][1]     = r[1];
                bfr[2 * hn + 1][0] = r[2];
                bfr[2 * hn + 1][1] = r[3];
            }
#pragma unroll
            for (int mt = 0; mt < 4; mt++) {
                int base = (warp_m * 64 + mt * 16 + g) * AS_H + ks * 16 + 2 * cth;
                uint32_t afr[4];
                afr[0] = *reinterpret_cast<const uint32_t*>(Ac + base);
                afr[1] = *reinterpret_cast<const uint32_t*>(Ac + base + 8 * AS_H);
                afr[2] = *reinterpret_cast<const uint32_t*>(Ac + base + 8);
                afr[3] = *reinterpret_cast<const uint32_t*>(Ac + base + 8 * AS_H + 8);
#pragma unroll
                for (int nt = 0; nt < 4; nt++)
                    mma_f16(acc[mt][nt], afr, bfr[nt]);
            }
        }
        __syncthreads();
    }

    // epilogue: fp32 acc + bias -> fp16 store
#pragma unroll
    for (int mt = 0; mt < 4; mt++) {
        int r0 = m_base + warp_m * 64 + mt * 16 + g;
        int r1 = r0 + 8;
#pragma unroll
        for (int nt = 0; nt < 4; nt++) {
            int col = n_base + warp_n * 32 + nt * 8 + cth * 2;
            float b0 = __ldg(bias + col);
            float b1 = __ldg(bias + col + 1);
            if (r0 < M) {
                uint32_t o = pack_h2(acc[mt][nt][0] + b0, acc[mt][nt][1] + b1);
                *reinterpret_cast<uint32_t*>(g_z16 + (size_t)r0 * HID + col) = o;
            }
            if (r1 < M) {
                uint32_t o = pack_h2(acc[mt][nt][2] + b0, acc[mt][nt][3] + b1);
                *reinterpret_cast<uint32_t*>(g_z16 + (size_t)r1 * HID + col) = o;
            }
        }
    }
}

// ---------------- fp16 gather-aggregate (CSR), warp per node, unroll 8 -------
__device__ __forceinline__ void acc_row(float* a, const uint4& v) {
    const uint32_t* w = &v.x;
#pragma unroll
    for (int j = 0; j < 4; j++) {
        float2 f = __half22float2(*reinterpret_cast<const __half2*>(w + j));
        a[2 * j]     += f.x;
        a[2 * j + 1] += f.y;
    }
}

__device__ __forceinline__ void gather_node16(int node, int lane, float* a /*[8]*/) {
    int start = g_off[node];
    int d     = g_deg[node];
    const uint4* Z = reinterpret_cast<const uint4*>(g_z16);   // 32 uint4 per row
#pragma unroll
    for (int j = 0; j < 8; j++) a[j] = 0.f;
    int i = 0;
    for (; i + 8 <= d; i += 8) {
        int s[8];
#pragma unroll
        for (int j = 0; j < 8; j++) s[j] = __ldg(&g_csr[start + i + j]);
        uint4 v[8];
#pragma unroll
        for (int j = 0; j < 8; j++) v[j] = __ldg(Z + (size_t)s[j] * 32 + lane);
#pragma unroll
        for (int j = 0; j < 8; j++) acc_row(a, v[j]);
    }
    for (; i < d; i++) {
        int s0 = __ldg(&g_csr[start + i]);
        uint4 v0 = __ldg(Z + (size_t)s0 * 32 + lane);
        acc_row(a, v0);
    }
}

__global__ void agg1_kernel() {
    int node = (blockIdx.x * blockDim.x + threadIdx.x) >> 5;
    int lane = threadIdx.x & 31;
    if (node >= NN) return;
    float a[8];
    gather_node16(node, lane, a);
    uint4 o;
    uint32_t* w = &o.x;
#pragma unroll
    for (int j = 0; j < 4; j++)
        w[j] = pack_h2(tanhf(a[2 * j]), tanhf(a[2 * j + 1]));
    reinterpret_cast<uint4*>(g_h16)[(size_t)node * 32 + lane] = o;
}

__global__ void agg2_pool_kernel(const int* __restrict__ seg) {
    int node = (blockIdx.x * blockDim.x + threadIdx.x) >> 5;
    int lane = threadIdx.x & 31;
    if (node >= NN) return;
    float a[8];
    gather_node16(node, lane, a);
    int s = __ldg(seg + node);
    float4* dp = reinterpret_cast<float4*>(g_sums + (size_t)s * HID + lane * 8);
    float4 t0 = make_float4(tanhf(a[0]), tanhf(a[1]), tanhf(a[2]), tanhf(a[3]));
    float4 t1 = make_float4(tanhf(a[4]), tanhf(a[5]), tanhf(a[6]), tanhf(a[7]));
    red_add_v4(dp,     t0);
    red_add_v4(dp + 1, t1);
    if (lane == 0) atomicAdd(&g_cnt[s], 1.0f);
}

__global__ void finalize_kernel(float* __restrict__ out) {
    int i = blockIdx.x * blockDim.x + threadIdx.x;
    if (i < NSLOTS * HID) {
        float c = g_cnt[i >> 8];
        out[i] = g_sums[i] / fmaxf(c, 1.0f);
    }
}

// ---------------- launch ----------------
extern "C" void kernel_launch(void* const* d_in, const int* in_sizes, int n_in,
                              void* d_out, int out_size) {
    const float* h    = (const float*)d_in[0];
    const float* W1   = (const float*)d_in[1];
    const float* b1   = (const float*)d_in[2];
    const float* W2   = (const float*)d_in[3];
    const float* b2   = (const float*)d_in[4];
    const int*   esrc = (const int*)d_in[5];
    const int*   edst = (const int*)d_in[6];
    const int*   seg  = (const int*)d_in[7];
    float*       out  = (float*)d_out;

    const int M = in_sizes[0] / HID;   // 100000

    static cudaStream_t s2 = nullptr;
    static cudaEvent_t  evA = nullptr, evB = nullptr;
    static int inited = 0;
    if (!inited) {
        cudaStreamCreateWithFlags(&s2, cudaStreamNonBlocking);
        cudaEventCreateWithFlags(&evA, cudaEventDisableTiming);
        cudaEventCreateWithFlags(&evB, cudaEventDisableTiming);
        cudaFuncSetAttribute(gemm_mma_kernel,
                             cudaFuncAttributeMaxDynamicSharedMemorySize,
                             GEMM_SMEM_BYTES);
        inited = 1;
    }

    dim3 gemm_grid(HID / 128, (M + 127) / 128);        // (2, 782)
    int  agg_blocks  = (M * 32 + 255) / 256;
    int  edge_blocks = (NE + 255) / 256;

    // ---- fork: CSR build on side stream ----
    cudaEventRecord(evA, 0);
    cudaStreamWaitEvent(s2, evA, 0);
    zero_misc_kernel<<<(NSLOTS * HID + 255) / 256, 256, 0, s2>>>();
    hist_kernel<<<edge_blocks, 256, 0, s2>>>(edst);
    scan1_kernel<<<NSCAN, 256, 0, s2>>>();
    scan2_kernel<<<1, 32, 0, s2>>>();
    scan3_kernel<<<NSCAN, 256, 0, s2>>>();
    fill_csr_kernel<<<edge_blocks, 256, 0, s2>>>(esrc, edst);
    cudaEventRecord(evB, s2);

    // ---- main stream: convert + GEMM1 (overlaps CSR build) ----
    conv_x_kernel<<<(NN * HID / 4) / 256, 256>>>(h);
    conv_w_kernel<<<128, 256>>>(W1, W2);
    gemm_mma_kernel<<<gemm_grid, 256, GEMM_SMEM_BYTES>>>(b1, M, 0, 0);

    // ---- join: CSR needed from here on ----
    cudaStreamWaitEvent(0, evB, 0);
    agg1_kernel<<<agg_blocks, 256>>>();

    gemm_mma_kernel<<<gemm_grid, 256, GEMM_SMEM_BYTES>>>(b2, M, 1, 1);
    agg2_pool_kernel<<<agg_blocks, 256>>>(seg);

    finalize_kernel<<<(NSLOTS * HID + 255) / 256, 256>>>(out);
}